// round 14
// baseline (speedup 1.0000x reference)
#include <cuda_runtime.h>
#include <cuda_fp16.h>
#include <cstdint>
#include <stdint.h>
#include <math.h>

// ---------------- problem dims (fixed) ----------------
#define DM    1024
#define DI    2048
#define DS    16
#define DTR   64
#define NB    2
#define LL    1024
#define NTOK  (NB*LL)        // 2048
#define XDBLC (DTR + 2*DS)   // 96

// ---------------- fp32 scratch ----------------
__device__ float g_XZ   [NTOK * 2 * DI];
__device__ float g_Xc   [NTOK * DI];
__device__ float g_XDBL [NTOK * XDBLC];
__device__ float g_DELTA[NTOK * DI];
__device__ float g_beta;

// ---------------- fp16 scratch (uint4 => 16B aligned) ----------------
__device__ uint4 g_hidH [NTOK*DM/8],   g_hidL [NTOK*DM/8];
__device__ uint4 g_WinH [2*DI*DM/8];
__device__ uint4 g_XcH  [NTOK*DI/8],   g_XcL  [NTOK*DI/8];
__device__ uint4 g_WxH  [XDBLC*DI/8];
__device__ uint4 g_XdH  [NTOK*XDBLC/8],g_XdL  [NTOK*XDBLC/8];
__device__ uint4 g_WdtH [DI*DTR/8];
__device__ uint4 g_YH   [NTOK*DI/8],   g_YL   [NTOK*DI/8];
__device__ uint4 g_WoutH[DM*DI/8];

// ---------------- helpers ----------------
__device__ __forceinline__ uint32_t smem_to_u32(const void* p) {
    uint32_t a;
    asm("{ .reg .u64 t; cvta.to.shared.u64 t, %1; cvt.u32.u64 %0, t; }" : "=r"(a) : "l"(p));
    return a;
}
__device__ __forceinline__ uint32_t swz(uint32_t r, uint32_t b) {
    return r * 128u + ((((b >> 4) ^ (r & 7u)) & 7u) << 4) + (b & 15u);
}
__device__ __forceinline__ void cp16(uint32_t dst, const void* src, bool v) {
    int sz = v ? 16 : 0;
    asm volatile("cp.async.cg.shared.global [%0], [%1], 16, %2;"
                 :: "r"(dst), "l"(src), "r"(sz) : "memory");
}
#define CP_COMMIT() asm volatile("cp.async.commit_group;" ::: "memory")
#define CP_WAIT1()  asm volatile("cp.async.wait_group 1;" ::: "memory")
#define CP_WAIT0()  asm volatile("cp.async.wait_group 0;" ::: "memory")

#define LDSM_X4(r0, r1, r2, r3, addr) \
    asm volatile("ldmatrix.sync.aligned.m8n8.x4.shared.b16 {%0,%1,%2,%3}, [%4];" \
                 : "=r"(r0), "=r"(r1), "=r"(r2), "=r"(r3) : "r"(addr))

__device__ __forceinline__ void mma16816(float* c, const uint32_t* a, const uint32_t* b) {
    asm("mma.sync.aligned.m16n8k16.row.col.f32.f16.f16.f32 "
        "{%0,%1,%2,%3}, {%4,%5,%6,%7}, {%8,%9}, {%0,%1,%2,%3};"
        : "+f"(c[0]), "+f"(c[1]), "+f"(c[2]), "+f"(c[3])
        : "r"(a[0]), "r"(a[1]), "r"(a[2]), "r"(a[3]), "r"(b[0]), "r"(b[1]));
}

// ---------------------------------------------------------------------------
// Split-fp16 tensor-core GEMM, 128x128 CTA tile, BK=64, 2-stage cp.async,
// 2 CTAs/SM (96KB smem). Split-K via blockIdx.z.
// epi mode: 0 = store, 1 = atomicAdd, 2 = softplus(acc + aux[col]) clip store
// grid = (ceil(N/128), M/128, ksplit)
// ---------------------------------------------------------------------------
#define STAGE_BYTES 49152
#define GEMM_SMEM   (2 * STAGE_BYTES)   // 98304

__device__ __forceinline__ void stage_load(
    uint32_t sb, const __half* Ah, const __half* Al, const __half* Bh,
    int row0, int col0, int lda, int ldb, int rowsB, int kc, int tid)
{
#pragma unroll
    for (int i = 0; i < 4; i++) {
        int idx = tid + i * 256;          // 0..1023
        uint32_t r = idx >> 3;            // row 0..127
        uint32_t c = idx & 7;             // 16B chunk 0..7
        uint32_t doff = swz(r, c * 16);
        size_t aoff = (size_t)(row0 + r) * lda * 2 + (size_t)kc * 128 + c * 16;
        cp16(sb + doff,         (const char*)Ah + aoff, true);
        cp16(sb + 16384 + doff, (const char*)Al + aoff, true);
        bool v = ((int)r < rowsB);
        uint32_t rb = v ? r : 0;
        size_t boff = (size_t)(col0 + rb) * ldb * 2 + (size_t)kc * 128 + c * 16;
        cp16(sb + 32768 + doff, (const char*)Bh + boff, v);
    }
}

__global__ __launch_bounds__(256, 2) void gemm_mma(
    const __half* __restrict__ Ah, const __half* __restrict__ Al,
    const __half* __restrict__ Bh,
    float* __restrict__ C, int kcn, int lda, int ldb, int ldc, int Nreal,
    int mode, const float* __restrict__ aux)
{
    extern __shared__ char smem[];
    const uint32_t smem_u = smem_to_u32(smem);
    const int tid  = threadIdx.x;
    const int lane = tid & 31;
    const int wid  = tid >> 5;
    const int wm   = wid & 3;    // 0..3 -> 32 rows each
    const int wn   = wid >> 2;   // 0..1 -> 64 cols each
    const int row0 = blockIdx.y * 128, col0 = blockIdx.x * 128;
    const int kc0  = blockIdx.z * kcn;

    int rowsB = Nreal - col0; if (rowsB > 128) rowsB = 128;

    float acc[2][8][4];
#pragma unroll
    for (int mt = 0; mt < 2; mt++)
#pragma unroll
        for (int nt = 0; nt < 8; nt++)
#pragma unroll
            for (int q = 0; q < 4; q++) acc[mt][nt][q] = 0.f;

    stage_load(smem_u, Ah, Al, Bh, row0, col0, lda, ldb, rowsB, kc0, tid);
    CP_COMMIT();
    if (kcn > 1) {
        stage_load(smem_u + STAGE_BYTES, Ah, Al, Bh, row0, col0, lda, ldb, rowsB, kc0 + 1, tid);
        CP_COMMIT();
    }

    const uint32_t rA_base = wm * 32 + (lane & 15);
    const uint32_t bA_lane = ((lane >> 4) << 4);
    const uint32_t rB_base = wn * 64 + ((lane >> 4) << 3) + (lane & 7);
    const uint32_t bB_lane = (((lane >> 3) & 1) << 4);

    for (int c2 = 0; c2 < kcn; c2++) {
        if (c2 + 1 < kcn) { CP_WAIT1(); } else { CP_WAIT0(); }
        __syncthreads();

        const uint32_t sb = smem_u + (uint32_t)(c2 & 1) * STAGE_BYTES;
#pragma unroll
        for (int ks = 0; ks < 4; ks++) {
            uint32_t ahf[2][4], alf[2][4], bhf[4][4];
#pragma unroll
            for (int mt = 0; mt < 2; mt++) {
                uint32_t aaddr = sb + swz(rA_base + mt * 16, ks * 32 + bA_lane);
                LDSM_X4(ahf[mt][0], ahf[mt][1], ahf[mt][2], ahf[mt][3], aaddr);
                LDSM_X4(alf[mt][0], alf[mt][1], alf[mt][2], alf[mt][3], aaddr + 16384);
            }
#pragma unroll
            for (int p = 0; p < 4; p++) {
                uint32_t baddr = sb + 32768 + swz(rB_base + p * 16, ks * 32 + bB_lane);
                LDSM_X4(bhf[p][0], bhf[p][1], bhf[p][2], bhf[p][3], baddr);
            }
#pragma unroll
            for (int mt = 0; mt < 2; mt++)
#pragma unroll
                for (int nt = 0; nt < 8; nt++) {
                    const uint32_t* b2h = &bhf[nt >> 1][(nt & 1) * 2];
                    mma16816(acc[mt][nt], ahf[mt], b2h);
                    mma16816(acc[mt][nt], alf[mt], b2h);
                }
        }
        __syncthreads();
        if (c2 + 2 < kcn) {
            stage_load(smem_u + (uint32_t)(c2 & 1) * STAGE_BYTES,
                       Ah, Al, Bh, row0, col0, lda, ldb, rowsB, kc0 + c2 + 2, tid);
            CP_COMMIT();
        }
    }

    // epilogue
    const int rr = row0 + wm * 32 + (lane >> 2);
    const int cc = col0 + wn * 64 + (lane & 3) * 2;
#pragma unroll
    for (int mt = 0; mt < 2; mt++)
#pragma unroll
        for (int nt = 0; nt < 8; nt++) {
            int colb = cc + nt * 8;
            if (colb < Nreal) {
                float* p0 = &C[(size_t)(rr + mt * 16)     * ldc + colb];
                float* p1 = &C[(size_t)(rr + mt * 16 + 8) * ldc + colb];
                if (mode == 1) {
                    atomicAdd(p0,     acc[mt][nt][0]);
                    atomicAdd(p0 + 1, acc[mt][nt][1]);
                    atomicAdd(p1,     acc[mt][nt][2]);
                    atomicAdd(p1 + 1, acc[mt][nt][3]);
                } else if (mode == 2) {
                    float b0 = aux[colb], b1 = aux[colb + 1];
                    float v[4] = { acc[mt][nt][0] + b0, acc[mt][nt][1] + b1,
                                   acc[mt][nt][2] + b0, acc[mt][nt][3] + b1 };
#pragma unroll
                    for (int q = 0; q < 4; q++) {
                        float sp = (v[q] > 20.f) ? v[q] : __logf(1.f + __expf(v[q]));
                        v[q] = fminf(fmaxf(sp, 1e-4f), 20.f);
                    }
                    *reinterpret_cast<float2*>(p0) = make_float2(v[0], v[1]);
                    *reinterpret_cast<float2*>(p1) = make_float2(v[2], v[3]);
                } else {
                    *reinterpret_cast<float2*>(p0) = make_float2(acc[mt][nt][0], acc[mt][nt][1]);
                    *reinterpret_cast<float2*>(p1) = make_float2(acc[mt][nt][2], acc[mt][nt][3]);
                }
            }
        }
}

// ---------------------------------------------------------------------------
// fp32 -> fp16 hi/lo split helpers
// ---------------------------------------------------------------------------
__device__ __forceinline__ void split1(float x, __half& h, __half& l) {
    h = __float2half_rn(x);
    l = __float2half_rn(x - __half2float(h));
}
__global__ void splitHL_kernel(const float* __restrict__ src,
                               __half* __restrict__ hi,
                               __half* __restrict__ lo, int n)
{
    int i = blockIdx.x * blockDim.x + threadIdx.x;
    if (i < n) split1(src[i], hi[i], lo[i]);
}

// ---------------------------------------------------------------------------
// fused prep: hidden hi/lo split + 4 weight fp16 casts + zero XDBL/out
// ---------------------------------------------------------------------------
#define P_N0 (NTOK*DM)
#define P_N1 (P_N0 + 2*DI*DM)
#define P_N2 (P_N1 + XDBLC*DI)
#define P_N3 (P_N2 + DI*DTR)
#define P_N4 (P_N3 + DM*DI)
#define P_N5 (P_N4 + NTOK*XDBLC)
#define P_N6 (P_N5 + NTOK*DM)
__global__ void prep_kernel(const float* __restrict__ hidden,
                            const float* __restrict__ W_in,
                            const float* __restrict__ W_x,
                            const float* __restrict__ W_dt,
                            const float* __restrict__ W_out,
                            __half* __restrict__ hidH, __half* __restrict__ hidL,
                            __half* __restrict__ WinH, __half* __restrict__ WxH,
                            __half* __restrict__ WdtH, __half* __restrict__ WoutH,
                            float* __restrict__ XDBL, float* __restrict__ out)
{
    int i = blockIdx.x * blockDim.x + threadIdx.x;
    if (i < P_N0)      { split1(hidden[i], hidH[i], hidL[i]); }
    else if (i < P_N1) { int j = i - P_N0; WinH[j]  = __float2half_rn(W_in[j]); }
    else if (i < P_N2) { int j = i - P_N1; WxH[j]   = __float2half_rn(W_x[j]); }
    else if (i < P_N3) { int j = i - P_N2; WdtH[j]  = __float2half_rn(W_dt[j]); }
    else if (i < P_N4) { int j = i - P_N3; WoutH[j] = __float2half_rn(W_out[j]); }
    else if (i < P_N5) { XDBL[i - P_N4] = 0.f; }
    else if (i < P_N6) { out[i - P_N5] = 0.f; }
}

// ---------------------------------------------------------------------------
// causal depthwise conv (k=4) + bias + silu, fused hi/lo split of output
// ---------------------------------------------------------------------------
__global__ void conv_silu_kernel(const float* __restrict__ XZ,
                                 const float* __restrict__ w,
                                 const float* __restrict__ cb,
                                 float* __restrict__ Xc,
                                 __half* __restrict__ XcH,
                                 __half* __restrict__ XcL)
{
    int idx = blockIdx.x * blockDim.x + threadIdx.x;
    if (idx >= NTOK * DI) return;
    int d = idx & (DI - 1);
    int token = idx >> 11;
    int b = token >> 10;
    int l = token & (LL - 1);

    float accv = cb[d];
#pragma unroll
    for (int j = 0; j < 4; j++) {
        int ll = l + j - 3;
        if (ll >= 0)
            accv = fmaf(w[d * 4 + j], XZ[(size_t)(b * LL + ll) * (2 * DI) + d], accv);
    }
    float s = __fdividef(accv, 1.f + __expf(-accv));
    Xc[idx] = s;
    split1(s, XcH[idx], XcL[idx]);
}

// ---------------------------------------------------------------------------
__global__ void beta_kernel(const float* __restrict__ XDBL)
{
    __shared__ float sm[1024];
    float mv = 3.0e38f;
    for (int i = threadIdx.x; i < NTOK * DS; i += 1024) {
        int token = i >> 4, n = i & 15;
        mv = fminf(mv, XDBL[token * XDBLC + DTR + n]);
    }
    sm[threadIdx.x] = mv;
    __syncthreads();
    for (int s = 512; s > 0; s >>= 1) {
        if (threadIdx.x < s) sm[threadIdx.x] = fminf(sm[threadIdx.x], sm[threadIdx.x + s]);
        __syncthreads();
    }
    if (threadIdx.x == 0) g_beta = fmaxf(0.f, -sm[0]);
}

// ---------------------------------------------------------------------------
// selective scan: 2 states/lane, 8 lanes/seq, 4 seqs/warp (1024 warps total),
// unroll-4 group prefetch, fused gating + hi/lo split of Y
// ---------------------------------------------------------------------------
#define UNR 4
__global__ __launch_bounds__(256) void scan_kernel(
    const float* __restrict__ XZ,   const float* __restrict__ XDBL,
    const float* __restrict__ DELTA,const float* __restrict__ Xc,
    const float* __restrict__ A_log,const float* __restrict__ Dv,
    __half* __restrict__ YH, __half* __restrict__ YL)
{
    int gtid = blockIdx.x * blockDim.x + threadIdx.x;
    int lane = gtid & 31;
    int warp = gtid >> 5;
    int seq  = warp * 4 + (lane >> 3);   // 0..4095, 4 seqs per warp (same b)
    int n0   = (lane & 7) * 2;           // states n0, n0+1
    int b    = seq >> 11;
    int d    = seq & (DI - 1);

    float a0 = __expf(A_log[d * DS + n0]);
    float a1 = __expf(A_log[d * DS + n0 + 1]);
    float beta = g_beta;
    float Dd   = Dv[d];
    float s0 = 0.f, s1 = 0.f;
    const int tok0 = b << 10;

    float  dc[UNR], xc[UNR], zc[UNR];
    float2 Bc[UNR], Cc[UNR];
#pragma unroll
    for (int u = 0; u < UNR; u++) {
        int t = tok0 + u;
        dc[u] = DELTA[(size_t)t * DI + d];
        xc[u] = Xc[(size_t)t * DI + d];
        zc[u] = XZ[(size_t)t * (2 * DI) + DI + d];
        Bc[u] = *(const float2*)&XDBL[(size_t)t * XDBLC + DTR + n0];
        Cc[u] = *(const float2*)&XDBL[(size_t)t * XDBLC + DTR + DS + n0];
    }

    for (int g = 0; g < LL / UNR; g++) {
        float  dn[UNR], xn[UNR], zn[UNR];
        float2 Bn[UNR], Cn[UNR];
        const int tnext = tok0 + (g + 1) * UNR;
        if (g + 1 < LL / UNR) {
#pragma unroll
            for (int u = 0; u < UNR; u++) {
                int t = tnext + u;
                dn[u] = DELTA[(size_t)t * DI + d];
                xn[u] = Xc[(size_t)t * DI + d];
                zn[u] = XZ[(size_t)t * (2 * DI) + DI + d];
                Bn[u] = *(const float2*)&XDBL[(size_t)t * XDBLC + DTR + n0];
                Cn[u] = *(const float2*)&XDBL[(size_t)t * XDBLC + DTR + DS + n0];
            }
        }
#pragma unroll
        for (int u = 0; u < UNR; u++) {
            float dx = dc[u] * xc[u];
            float dA0 = __expf(-dc[u] * a0);
            float dA1 = __expf(-dc[u] * a1);
            s0 = fmaf(dA0, s0, dx * (Bc[u].x + beta));
            s1 = fmaf(dA1, s1, dx * (Bc[u].y + beta));
            float p = fmaf(s0, Cc[u].x, s1 * Cc[u].y);
            p += __shfl_xor_sync(0xffffffffu, p, 1);
            p += __shfl_xor_sync(0xffffffffu, p, 2);
            p += __shfl_xor_sync(0xffffffffu, p, 4);
            if ((lane & 7) == 0) {
                float zz = zc[u];
                float sz = __fdividef(zz, 1.f + __expf(-zz));
                float yv = (p + xc[u] * Dd) * sz;
                size_t oi = (size_t)(tok0 + g * UNR + u) * DI + d;
                split1(yv, YH[oi], YL[oi]);
            }
        }
#pragma unroll
        for (int u = 0; u < UNR; u++) {
            dc[u] = dn[u]; xc[u] = xn[u]; zc[u] = zn[u]; Bc[u] = Bn[u]; Cc[u] = Cn[u];
        }
    }
}

// ---------------------------------------------------------------------------
extern "C" void kernel_launch(void* const* d_in, const int* in_sizes, int n_in,
                              void* d_out, int out_size)
{
    const float* hidden  = (const float*)d_in[0];
    const float* W_in    = (const float*)d_in[1];
    const float* conv_w  = (const float*)d_in[2];
    const float* conv_b  = (const float*)d_in[3];
    const float* W_x     = (const float*)d_in[4];
    const float* W_dt    = (const float*)d_in[5];
    const float* dt_bias = (const float*)d_in[6];
    const float* W_out   = (const float*)d_in[7];
    const float* A_log   = (const float*)d_in[8];
    const float* Dv      = (const float*)d_in[9];
    float* out = (float*)d_out;

    float *XZ, *Xc, *XDBL, *DELTA;
    cudaGetSymbolAddress((void**)&XZ,    g_XZ);
    cudaGetSymbolAddress((void**)&Xc,    g_Xc);
    cudaGetSymbolAddress((void**)&XDBL,  g_XDBL);
    cudaGetSymbolAddress((void**)&DELTA, g_DELTA);

    __half *hidH,*hidL,*WinH,*XcH,*XcL,*WxH,*XdH,*XdL,*WdtH,*YH,*YL,*WoutH;
    cudaGetSymbolAddress((void**)&hidH,  g_hidH);  cudaGetSymbolAddress((void**)&hidL,  g_hidL);
    cudaGetSymbolAddress((void**)&WinH,  g_WinH);
    cudaGetSymbolAddress((void**)&XcH,   g_XcH);   cudaGetSymbolAddress((void**)&XcL,   g_XcL);
    cudaGetSymbolAddress((void**)&WxH,   g_WxH);
    cudaGetSymbolAddress((void**)&XdH,   g_XdH);   cudaGetSymbolAddress((void**)&XdL,   g_XdL);
    cudaGetSymbolAddress((void**)&WdtH,  g_WdtH);
    cudaGetSymbolAddress((void**)&YH,    g_YH);    cudaGetSymbolAddress((void**)&YL,    g_YL);
    cudaGetSymbolAddress((void**)&WoutH, g_WoutH);

    cudaFuncSetAttribute(gemm_mma, cudaFuncAttributeMaxDynamicSharedMemorySize, GEMM_SMEM);

    // 0) fused prep: splits + zeros
    prep_kernel<<<(P_N6 + 255)/256, 256>>>(hidden, W_in, W_x, W_dt, W_out,
                                           hidH, hidL, WinH, WxH, WdtH, WoutH,
                                           XDBL, out);

    // 1) xz = hidden @ W_in^T   (M=2048, N=4096, K=1024)
    gemm_mma<<<dim3(4096/128, NTOK/128, 1), 256, GEMM_SMEM>>>(
        hidH, hidL, WinH, XZ, 16, DM, DM, 2*DI, 2*DI, 0, nullptr);

    // 2) conv + silu (+ split)
    conv_silu_kernel<<<(NTOK*DI)/256, 256>>>(XZ, conv_w, conv_b, Xc, XcH, XcL);

    // 3) x_dbl = Xc @ W_x^T     (M=2048, N=96 pad 128, K=2048, split-K x8)
    gemm_mma<<<dim3(1, NTOK/128, 8), 256, GEMM_SMEM>>>(
        XcH, XcL, WxH, XDBL, 4, DI, DI, XDBLC, XDBLC, 1, nullptr);

    // split x_dbl for GEMM4
    splitHL_kernel<<<(NTOK*XDBLC + 255)/256, 256>>>(XDBL, XdH, XdL, NTOK*XDBLC);

    // 4) dt = x_dbl[:, :64] @ W_dt^T  (K=64; lda=96) with fused softplus+clip
    gemm_mma<<<dim3(DI/128, NTOK/128, 1), 256, GEMM_SMEM>>>(
        XdH, XdL, WdtH, DELTA, 1, XDBLC, DTR, DI, DI, 2, dt_bias);

    // 5) beta
    beta_kernel<<<1, 1024>>>(XDBL);

    // 6) scan (+ gating + split)  — 1024 warps = 128 blocks of 256
    scan_kernel<<<128, 256>>>(XZ, XDBL, DELTA, Xc, A_log, Dv, YH, YL);

    // 7) out = Y @ W_out^T      (M=2048, N=1024, K=2048, split-K x2)
    gemm_mma<<<dim3(DM/128, NTOK/128, 2), 256, GEMM_SMEM>>>(
        YH, YL, WoutH, out, 16, DI, DI, DM, DM, 1, nullptr);
}

// round 15
// speedup vs baseline: 1.4307x; 1.4307x over previous
#include <cuda_runtime.h>
#include <cuda_fp16.h>
#include <cstdint>
#include <stdint.h>
#include <math.h>

// ---------------- problem dims (fixed) ----------------
#define DM    1024
#define DI    2048
#define DS    16
#define DTR   64
#define NB    2
#define LL    1024
#define NTOK  (NB*LL)        // 2048
#define XDBLC (DTR + 2*DS)   // 96

// ---------------- fp32 scratch ----------------
__device__ float g_XZ   [NTOK * 2 * DI];
__device__ float g_Xc   [NTOK * DI];
__device__ float g_XDBL [NTOK * XDBLC];
__device__ float g_DELTA[NTOK * DI];
__device__ float g_beta;

// ---------------- fp16 scratch (uint4 => 16B aligned) ----------------
__device__ uint4 g_hidH [NTOK*DM/8],   g_hidL [NTOK*DM/8];
__device__ uint4 g_WinH [2*DI*DM/8];
__device__ uint4 g_XcH  [NTOK*DI/8],   g_XcL  [NTOK*DI/8];
__device__ uint4 g_WxH  [XDBLC*DI/8];
__device__ uint4 g_XdH  [NTOK*XDBLC/8],g_XdL  [NTOK*XDBLC/8];
__device__ uint4 g_WdtH [DI*DTR/8];
__device__ uint4 g_YH   [NTOK*DI/8],   g_YL   [NTOK*DI/8];
__device__ uint4 g_WoutH[DM*DI/8];

// ---------------- helpers ----------------
__device__ __forceinline__ uint32_t smem_to_u32(const void* p) {
    uint32_t a;
    asm("{ .reg .u64 t; cvta.to.shared.u64 t, %1; cvt.u32.u64 %0, t; }" : "=r"(a) : "l"(p));
    return a;
}
__device__ __forceinline__ uint32_t swz(uint32_t r, uint32_t b) {
    return r * 128u + ((((b >> 4) ^ (r & 7u)) & 7u) << 4) + (b & 15u);
}
__device__ __forceinline__ void cp16(uint32_t dst, const void* src, bool v) {
    int sz = v ? 16 : 0;
    asm volatile("cp.async.cg.shared.global [%0], [%1], 16, %2;"
                 :: "r"(dst), "l"(src), "r"(sz) : "memory");
}
#define CP_COMMIT() asm volatile("cp.async.commit_group;" ::: "memory")
#define CP_WAIT1()  asm volatile("cp.async.wait_group 1;" ::: "memory")
#define CP_WAIT0()  asm volatile("cp.async.wait_group 0;" ::: "memory")

#define LDSM_X4(r0, r1, r2, r3, addr) \
    asm volatile("ldmatrix.sync.aligned.m8n8.x4.shared.b16 {%0,%1,%2,%3}, [%4];" \
                 : "=r"(r0), "=r"(r1), "=r"(r2), "=r"(r3) : "r"(addr))

__device__ __forceinline__ void mma16816(float* c, const uint32_t* a, const uint32_t* b) {
    asm("mma.sync.aligned.m16n8k16.row.col.f32.f16.f16.f32 "
        "{%0,%1,%2,%3}, {%4,%5,%6,%7}, {%8,%9}, {%0,%1,%2,%3};"
        : "+f"(c[0]), "+f"(c[1]), "+f"(c[2]), "+f"(c[3])
        : "r"(a[0]), "r"(a[1]), "r"(a[2]), "r"(a[3]), "r"(b[0]), "r"(b[1]));
}

// ---------------------------------------------------------------------------
// Split-fp16 tensor-core GEMM, 128x128 CTA tile, BK=64, 2-stage cp.async,
// 2 CTAs/SM (96KB smem). Split-K via blockIdx.z.
// epi mode: 0 = store, 1 = atomicAdd, 2 = softplus(acc + aux[col]) clip store
// grid = (ceil(N/128), M/128, ksplit)
// ---------------------------------------------------------------------------
#define STAGE_BYTES 49152
#define GEMM_SMEM   (2 * STAGE_BYTES)   // 98304

__device__ __forceinline__ void stage_load(
    uint32_t sb, const __half* Ah, const __half* Al, const __half* Bh,
    int row0, int col0, int lda, int ldb, int rowsB, int kc, int tid)
{
#pragma unroll
    for (int i = 0; i < 4; i++) {
        int idx = tid + i * 256;          // 0..1023
        uint32_t r = idx >> 3;            // row 0..127
        uint32_t c = idx & 7;             // 16B chunk 0..7
        uint32_t doff = swz(r, c * 16);
        size_t aoff = (size_t)(row0 + r) * lda * 2 + (size_t)kc * 128 + c * 16;
        cp16(sb + doff,         (const char*)Ah + aoff, true);
        cp16(sb + 16384 + doff, (const char*)Al + aoff, true);
        bool v = ((int)r < rowsB);
        uint32_t rb = v ? r : 0;
        size_t boff = (size_t)(col0 + rb) * ldb * 2 + (size_t)kc * 128 + c * 16;
        cp16(sb + 32768 + doff, (const char*)Bh + boff, v);
    }
}

__global__ __launch_bounds__(256, 2) void gemm_mma(
    const __half* __restrict__ Ah, const __half* __restrict__ Al,
    const __half* __restrict__ Bh,
    float* __restrict__ C, int kcn, int lda, int ldb, int ldc, int Nreal,
    int mode, const float* __restrict__ aux)
{
    extern __shared__ char smem[];
    const uint32_t smem_u = smem_to_u32(smem);
    const int tid  = threadIdx.x;
    const int lane = tid & 31;
    const int wid  = tid >> 5;
    const int wm   = wid & 3;    // 0..3 -> 32 rows each
    const int wn   = wid >> 2;   // 0..1 -> 64 cols each
    const int row0 = blockIdx.y * 128, col0 = blockIdx.x * 128;
    const int kc0  = blockIdx.z * kcn;

    int rowsB = Nreal - col0; if (rowsB > 128) rowsB = 128;

    float acc[2][8][4];
#pragma unroll
    for (int mt = 0; mt < 2; mt++)
#pragma unroll
        for (int nt = 0; nt < 8; nt++)
#pragma unroll
            for (int q = 0; q < 4; q++) acc[mt][nt][q] = 0.f;

    stage_load(smem_u, Ah, Al, Bh, row0, col0, lda, ldb, rowsB, kc0, tid);
    CP_COMMIT();
    if (kcn > 1) {
        stage_load(smem_u + STAGE_BYTES, Ah, Al, Bh, row0, col0, lda, ldb, rowsB, kc0 + 1, tid);
        CP_COMMIT();
    }

    const uint32_t rA_base = wm * 32 + (lane & 15);
    const uint32_t bA_lane = ((lane >> 4) << 4);
    const uint32_t rB_base = wn * 64 + ((lane >> 4) << 3) + (lane & 7);
    const uint32_t bB_lane = (((lane >> 3) & 1) << 4);

    for (int c2 = 0; c2 < kcn; c2++) {
        if (c2 + 1 < kcn) { CP_WAIT1(); } else { CP_WAIT0(); }
        __syncthreads();

        const uint32_t sb = smem_u + (uint32_t)(c2 & 1) * STAGE_BYTES;
#pragma unroll
        for (int ks = 0; ks < 4; ks++) {
            uint32_t ahf[2][4], alf[2][4], bhf[4][4];
#pragma unroll
            for (int mt = 0; mt < 2; mt++) {
                uint32_t aaddr = sb + swz(rA_base + mt * 16, ks * 32 + bA_lane);
                LDSM_X4(ahf[mt][0], ahf[mt][1], ahf[mt][2], ahf[mt][3], aaddr);
                LDSM_X4(alf[mt][0], alf[mt][1], alf[mt][2], alf[mt][3], aaddr + 16384);
            }
#pragma unroll
            for (int p = 0; p < 4; p++) {
                uint32_t baddr = sb + 32768 + swz(rB_base + p * 16, ks * 32 + bB_lane);
                LDSM_X4(bhf[p][0], bhf[p][1], bhf[p][2], bhf[p][3], baddr);
            }
#pragma unroll
            for (int mt = 0; mt < 2; mt++)
#pragma unroll
                for (int nt = 0; nt < 8; nt++) {
                    const uint32_t* b2h = &bhf[nt >> 1][(nt & 1) * 2];
                    mma16816(acc[mt][nt], ahf[mt], b2h);
                    mma16816(acc[mt][nt], alf[mt], b2h);
                }
        }
        __syncthreads();
        if (c2 + 2 < kcn) {
            stage_load(smem_u + (uint32_t)(c2 & 1) * STAGE_BYTES,
                       Ah, Al, Bh, row0, col0, lda, ldb, rowsB, kc0 + c2 + 2, tid);
            CP_COMMIT();
        }
    }

    // epilogue
    const int rr = row0 + wm * 32 + (lane >> 2);
    const int cc = col0 + wn * 64 + (lane & 3) * 2;
#pragma unroll
    for (int mt = 0; mt < 2; mt++)
#pragma unroll
        for (int nt = 0; nt < 8; nt++) {
            int colb = cc + nt * 8;
            if (colb < Nreal) {
                float* p0 = &C[(size_t)(rr + mt * 16)     * ldc + colb];
                float* p1 = &C[(size_t)(rr + mt * 16 + 8) * ldc + colb];
                if (mode == 1) {
                    atomicAdd(p0,     acc[mt][nt][0]);
                    atomicAdd(p0 + 1, acc[mt][nt][1]);
                    atomicAdd(p1,     acc[mt][nt][2]);
                    atomicAdd(p1 + 1, acc[mt][nt][3]);
                } else if (mode == 2) {
                    float b0 = aux[colb], b1 = aux[colb + 1];
                    float v[4] = { acc[mt][nt][0] + b0, acc[mt][nt][1] + b1,
                                   acc[mt][nt][2] + b0, acc[mt][nt][3] + b1 };
#pragma unroll
                    for (int q = 0; q < 4; q++) {
                        float sp = (v[q] > 20.f) ? v[q] : __logf(1.f + __expf(v[q]));
                        v[q] = fminf(fmaxf(sp, 1e-4f), 20.f);
                    }
                    *reinterpret_cast<float2*>(p0) = make_float2(v[0], v[1]);
                    *reinterpret_cast<float2*>(p1) = make_float2(v[2], v[3]);
                } else {
                    *reinterpret_cast<float2*>(p0) = make_float2(acc[mt][nt][0], acc[mt][nt][1]);
                    *reinterpret_cast<float2*>(p1) = make_float2(acc[mt][nt][2], acc[mt][nt][3]);
                }
            }
        }
}

// ---------------------------------------------------------------------------
// fp32 -> fp16 hi/lo split helpers
// ---------------------------------------------------------------------------
__device__ __forceinline__ void split1(float x, __half& h, __half& l) {
    h = __float2half_rn(x);
    l = __float2half_rn(x - __half2float(h));
}
__global__ void splitHL_kernel(const float* __restrict__ src,
                               __half* __restrict__ hi,
                               __half* __restrict__ lo, int n)
{
    int i = blockIdx.x * blockDim.x + threadIdx.x;
    if (i < n) split1(src[i], hi[i], lo[i]);
}

// ---------------------------------------------------------------------------
// fused prep: hidden hi/lo split + 4 weight fp16 casts + zero XDBL/out
// ---------------------------------------------------------------------------
#define P_N0 (NTOK*DM)
#define P_N1 (P_N0 + 2*DI*DM)
#define P_N2 (P_N1 + XDBLC*DI)
#define P_N3 (P_N2 + DI*DTR)
#define P_N4 (P_N3 + DM*DI)
#define P_N5 (P_N4 + NTOK*XDBLC)
#define P_N6 (P_N5 + NTOK*DM)
__global__ void prep_kernel(const float* __restrict__ hidden,
                            const float* __restrict__ W_in,
                            const float* __restrict__ W_x,
                            const float* __restrict__ W_dt,
                            const float* __restrict__ W_out,
                            __half* __restrict__ hidH, __half* __restrict__ hidL,
                            __half* __restrict__ WinH, __half* __restrict__ WxH,
                            __half* __restrict__ WdtH, __half* __restrict__ WoutH,
                            float* __restrict__ XDBL, float* __restrict__ out)
{
    int i = blockIdx.x * blockDim.x + threadIdx.x;
    if (i < P_N0)      { split1(hidden[i], hidH[i], hidL[i]); }
    else if (i < P_N1) { int j = i - P_N0; WinH[j]  = __float2half_rn(W_in[j]); }
    else if (i < P_N2) { int j = i - P_N1; WxH[j]   = __float2half_rn(W_x[j]); }
    else if (i < P_N3) { int j = i - P_N2; WdtH[j]  = __float2half_rn(W_dt[j]); }
    else if (i < P_N4) { int j = i - P_N3; WoutH[j] = __float2half_rn(W_out[j]); }
    else if (i < P_N5) { XDBL[i - P_N4] = 0.f; }
    else if (i < P_N6) { out[i - P_N5] = 0.f; }
}

// ---------------------------------------------------------------------------
// causal depthwise conv (k=4) + bias + silu, fused hi/lo split of output
// ---------------------------------------------------------------------------
__global__ void conv_silu_kernel(const float* __restrict__ XZ,
                                 const float* __restrict__ w,
                                 const float* __restrict__ cb,
                                 float* __restrict__ Xc,
                                 __half* __restrict__ XcH,
                                 __half* __restrict__ XcL)
{
    int idx = blockIdx.x * blockDim.x + threadIdx.x;
    if (idx >= NTOK * DI) return;
    int d = idx & (DI - 1);
    int token = idx >> 11;
    int b = token >> 10;
    int l = token & (LL - 1);

    float accv = cb[d];
#pragma unroll
    for (int j = 0; j < 4; j++) {
        int ll = l + j - 3;
        if (ll >= 0)
            accv = fmaf(w[d * 4 + j], XZ[(size_t)(b * LL + ll) * (2 * DI) + d], accv);
    }
    float s = __fdividef(accv, 1.f + __expf(-accv));
    Xc[idx] = s;
    split1(s, XcH[idx], XcL[idx]);
}

// ---------------------------------------------------------------------------
__global__ void beta_kernel(const float* __restrict__ XDBL)
{
    __shared__ float sm[1024];
    float mv = 3.0e38f;
    for (int i = threadIdx.x; i < NTOK * DS; i += 1024) {
        int token = i >> 4, n = i & 15;
        mv = fminf(mv, XDBL[token * XDBLC + DTR + n]);
    }
    sm[threadIdx.x] = mv;
    __syncthreads();
    for (int s = 512; s > 0; s >>= 1) {
        if (threadIdx.x < s) sm[threadIdx.x] = fminf(sm[threadIdx.x], sm[threadIdx.x + s]);
        __syncthreads();
    }
    if (threadIdx.x == 0) g_beta = fmaxf(0.f, -sm[0]);
}

// ---------------------------------------------------------------------------
// selective scan (16 lanes per sequence, 2 seqs/warp, 2048 warps),
// unroll-4 group prefetch, fused gating + hi/lo split of Y   [R9-exact]
// ---------------------------------------------------------------------------
#define UNR 4
__global__ __launch_bounds__(256) void scan_kernel(
    const float* __restrict__ XZ,   const float* __restrict__ XDBL,
    const float* __restrict__ DELTA,const float* __restrict__ Xc,
    const float* __restrict__ A_log,const float* __restrict__ Dv,
    __half* __restrict__ YH, __half* __restrict__ YL)
{
    int gtid = blockIdx.x * blockDim.x + threadIdx.x;
    int lane = gtid & 31;
    int warp = gtid >> 5;
    int seq  = warp * 2 + (lane >> 4);
    int n    = lane & 15;
    int b    = seq >> 11;
    int d    = seq & (DI - 1);

    float a    = __expf(A_log[d * DS + n]);
    float beta = g_beta;
    float Dd   = Dv[d];
    float state = 0.f;
    const int tok0 = b << 10;

    float dc[UNR], xc[UNR], Bc[UNR], Cc[UNR], zc[UNR];
#pragma unroll
    for (int u = 0; u < UNR; u++) {
        int t = tok0 + u;
        dc[u] = DELTA[(size_t)t * DI + d];
        xc[u] = Xc[(size_t)t * DI + d];
        Bc[u] = XDBL[(size_t)t * XDBLC + DTR + n];
        Cc[u] = XDBL[(size_t)t * XDBLC + DTR + DS + n];
        zc[u] = XZ[(size_t)t * (2 * DI) + DI + d];
    }

    for (int g = 0; g < LL / UNR; g++) {
        float dn[UNR], xn[UNR], Bn[UNR], Cn[UNR], zn[UNR];
        const int tnext = tok0 + (g + 1) * UNR;
        if (g + 1 < LL / UNR) {
#pragma unroll
            for (int u = 0; u < UNR; u++) {
                int t = tnext + u;
                dn[u] = DELTA[(size_t)t * DI + d];
                xn[u] = Xc[(size_t)t * DI + d];
                Bn[u] = XDBL[(size_t)t * XDBLC + DTR + n];
                Cn[u] = XDBL[(size_t)t * XDBLC + DTR + DS + n];
                zn[u] = XZ[(size_t)t * (2 * DI) + DI + d];
            }
        }
#pragma unroll
        for (int u = 0; u < UNR; u++) {
            float dA = __expf(-dc[u] * a);
            state = fmaf(dA, state, (dc[u] * xc[u]) * (Bc[u] + beta));
            float p = state * Cc[u];
            p += __shfl_xor_sync(0xffffffffu, p, 1);
            p += __shfl_xor_sync(0xffffffffu, p, 2);
            p += __shfl_xor_sync(0xffffffffu, p, 4);
            p += __shfl_xor_sync(0xffffffffu, p, 8);
            if (n == 0) {
                float zz = zc[u];
                float sz = __fdividef(zz, 1.f + __expf(-zz));
                float yv = (p + xc[u] * Dd) * sz;
                size_t oi = (size_t)(tok0 + g * UNR + u) * DI + d;
                split1(yv, YH[oi], YL[oi]);
            }
        }
#pragma unroll
        for (int u = 0; u < UNR; u++) {
            dc[u] = dn[u]; xc[u] = xn[u]; Bc[u] = Bn[u]; Cc[u] = Cn[u]; zc[u] = zn[u];
        }
    }
}

// ---------------------------------------------------------------------------
extern "C" void kernel_launch(void* const* d_in, const int* in_sizes, int n_in,
                              void* d_out, int out_size)
{
    const float* hidden  = (const float*)d_in[0];
    const float* W_in    = (const float*)d_in[1];
    const float* conv_w  = (const float*)d_in[2];
    const float* conv_b  = (const float*)d_in[3];
    const float* W_x     = (const float*)d_in[4];
    const float* W_dt    = (const float*)d_in[5];
    const float* dt_bias = (const float*)d_in[6];
    const float* W_out   = (const float*)d_in[7];
    const float* A_log   = (const float*)d_in[8];
    const float* Dv      = (const float*)d_in[9];
    float* out = (float*)d_out;

    float *XZ, *Xc, *XDBL, *DELTA;
    cudaGetSymbolAddress((void**)&XZ,    g_XZ);
    cudaGetSymbolAddress((void**)&Xc,    g_Xc);
    cudaGetSymbolAddress((void**)&XDBL,  g_XDBL);
    cudaGetSymbolAddress((void**)&DELTA, g_DELTA);

    __half *hidH,*hidL,*WinH,*XcH,*XcL,*WxH,*XdH,*XdL,*WdtH,*YH,*YL,*WoutH;
    cudaGetSymbolAddress((void**)&hidH,  g_hidH);  cudaGetSymbolAddress((void**)&hidL,  g_hidL);
    cudaGetSymbolAddress((void**)&WinH,  g_WinH);
    cudaGetSymbolAddress((void**)&XcH,   g_XcH);   cudaGetSymbolAddress((void**)&XcL,   g_XcL);
    cudaGetSymbolAddress((void**)&WxH,   g_WxH);
    cudaGetSymbolAddress((void**)&XdH,   g_XdH);   cudaGetSymbolAddress((void**)&XdL,   g_XdL);
    cudaGetSymbolAddress((void**)&WdtH,  g_WdtH);
    cudaGetSymbolAddress((void**)&YH,    g_YH);    cudaGetSymbolAddress((void**)&YL,    g_YL);
    cudaGetSymbolAddress((void**)&WoutH, g_WoutH);

    cudaFuncSetAttribute(gemm_mma, cudaFuncAttributeMaxDynamicSharedMemorySize, GEMM_SMEM);

    // 0) fused prep: splits + zeros
    prep_kernel<<<(P_N6 + 255)/256, 256>>>(hidden, W_in, W_x, W_dt, W_out,
                                           hidH, hidL, WinH, WxH, WdtH, WoutH,
                                           XDBL, out);

    // 1) xz = hidden @ W_in^T   (M=2048, N=4096, K=1024)
    gemm_mma<<<dim3(4096/128, NTOK/128, 1), 256, GEMM_SMEM>>>(
        hidH, hidL, WinH, XZ, 16, DM, DM, 2*DI, 2*DI, 0, nullptr);

    // 2) conv + silu (+ split)
    conv_silu_kernel<<<(NTOK*DI)/256, 256>>>(XZ, conv_w, conv_b, Xc, XcH, XcL);

    // 3) x_dbl = Xc @ W_x^T     (M=2048, N=96 pad 128, K=2048, split-K x4)  [R9]
    gemm_mma<<<dim3(1, NTOK/128, 4), 256, GEMM_SMEM>>>(
        XcH, XcL, WxH, XDBL, 8, DI, DI, XDBLC, XDBLC, 1, nullptr);

    // split x_dbl for GEMM4
    splitHL_kernel<<<(NTOK*XDBLC + 255)/256, 256>>>(XDBL, XdH, XdL, NTOK*XDBLC);

    // 4) dt = x_dbl[:, :64] @ W_dt^T  (K=64; lda=96) with fused softplus+clip
    gemm_mma<<<dim3(DI/128, NTOK/128, 1), 256, GEMM_SMEM>>>(
        XdH, XdL, WdtH, DELTA, 1, XDBLC, DTR, DI, DI, 2, dt_bias);

    // 5) beta
    beta_kernel<<<1, 1024>>>(XDBL);

    // 6) scan (+ gating + split)  [R9-exact: 2048 warps]
    scan_kernel<<<(NB*DI*DS)/256, 256>>>(XZ, XDBL, DELTA, Xc, A_log, Dv, YH, YL);

    // 7) out = Y @ W_out^T      (M=2048, N=1024, K=2048, split-K x2)  [R9]
    gemm_mma<<<dim3(DM/128, NTOK/128, 2), 256, GEMM_SMEM>>>(
        YH, YL, WoutH, out, 16, DI, DI, DM, DM, 1, nullptr);
}

// round 16
// speedup vs baseline: 1.6312x; 1.1402x over previous
#include <cuda_runtime.h>
#include <cuda_fp16.h>
#include <cstdint>
#include <stdint.h>
#include <math.h>

// ---------------- problem dims (fixed) ----------------
#define DM    1024
#define DI    2048
#define DS    16
#define DTR   64
#define NB    2
#define LL    1024
#define NTOK  (NB*LL)        // 2048
#define XDBLC (DTR + 2*DS)   // 96

// ---------------- fp32 scratch ----------------
__device__ float g_XZ   [NTOK * 2 * DI];
__device__ float g_Xc   [NTOK * DI];
__device__ float g_XDBL [NTOK * XDBLC];
__device__ float g_DELTA[NTOK * DI];
__device__ float g_DT_T [NTOK * DI];   // [d][token]
__device__ float g_XcT  [NTOK * DI];   // [d][token]
__device__ float g_ZT   [NTOK * DI];   // [d][token]
__device__ unsigned g_betaBits;

// ---------------- fp16 scratch (uint4 => 16B aligned) ----------------
__device__ uint4 g_hidH [NTOK*DM/8],   g_hidL [NTOK*DM/8];
__device__ uint4 g_WinH [2*DI*DM/8];
__device__ uint4 g_XcH  [NTOK*DI/8],   g_XcL  [NTOK*DI/8];
__device__ uint4 g_WxH  [XDBLC*DI/8];
__device__ uint4 g_XdH  [NTOK*XDBLC/8],g_XdL  [NTOK*XDBLC/8];
__device__ uint4 g_WdtH [DI*DTR/8];
__device__ uint4 g_YH   [NTOK*DI/8],   g_YL   [NTOK*DI/8];
__device__ uint4 g_WoutH[DM*DI/8];

// ---------------- helpers ----------------
__device__ __forceinline__ uint32_t smem_to_u32(const void* p) {
    uint32_t a;
    asm("{ .reg .u64 t; cvta.to.shared.u64 t, %1; cvt.u32.u64 %0, t; }" : "=r"(a) : "l"(p));
    return a;
}
__device__ __forceinline__ uint32_t swz(uint32_t r, uint32_t b) {
    return r * 128u + ((((b >> 4) ^ (r & 7u)) & 7u) << 4) + (b & 15u);
}
__device__ __forceinline__ void cp16(uint32_t dst, const void* src, bool v) {
    int sz = v ? 16 : 0;
    asm volatile("cp.async.cg.shared.global [%0], [%1], 16, %2;"
                 :: "r"(dst), "l"(src), "r"(sz) : "memory");
}
#define CP_COMMIT() asm volatile("cp.async.commit_group;" ::: "memory")
#define CP_WAIT1()  asm volatile("cp.async.wait_group 1;" ::: "memory")
#define CP_WAIT0()  asm volatile("cp.async.wait_group 0;" ::: "memory")

#define LDSM_X4(r0, r1, r2, r3, addr) \
    asm volatile("ldmatrix.sync.aligned.m8n8.x4.shared.b16 {%0,%1,%2,%3}, [%4];" \
                 : "=r"(r0), "=r"(r1), "=r"(r2), "=r"(r3) : "r"(addr))

__device__ __forceinline__ void mma16816(float* c, const uint32_t* a, const uint32_t* b) {
    asm("mma.sync.aligned.m16n8k16.row.col.f32.f16.f16.f32 "
        "{%0,%1,%2,%3}, {%4,%5,%6,%7}, {%8,%9}, {%0,%1,%2,%3};"
        : "+f"(c[0]), "+f"(c[1]), "+f"(c[2]), "+f"(c[3])
        : "r"(a[0]), "r"(a[1]), "r"(a[2]), "r"(a[3]), "r"(b[0]), "r"(b[1]));
}

// ---------------------------------------------------------------------------
// Split-fp16 tensor-core GEMM, 128x128 CTA tile, BK=64, 2-stage cp.async,
// 2 CTAs/SM (96KB smem). Split-K via blockIdx.z.   [R15-exact]
// epi mode: 0 = store, 1 = atomicAdd, 2 = softplus(acc + aux[col]) clip store
// ---------------------------------------------------------------------------
#define STAGE_BYTES 49152
#define GEMM_SMEM   (2 * STAGE_BYTES)   // 98304

__device__ __forceinline__ void stage_load(
    uint32_t sb, const __half* Ah, const __half* Al, const __half* Bh,
    int row0, int col0, int lda, int ldb, int rowsB, int kc, int tid)
{
#pragma unroll
    for (int i = 0; i < 4; i++) {
        int idx = tid + i * 256;          // 0..1023
        uint32_t r = idx >> 3;            // row 0..127
        uint32_t c = idx & 7;             // 16B chunk 0..7
        uint32_t doff = swz(r, c * 16);
        size_t aoff = (size_t)(row0 + r) * lda * 2 + (size_t)kc * 128 + c * 16;
        cp16(sb + doff,         (const char*)Ah + aoff, true);
        cp16(sb + 16384 + doff, (const char*)Al + aoff, true);
        bool v = ((int)r < rowsB);
        uint32_t rb = v ? r : 0;
        size_t boff = (size_t)(col0 + rb) * ldb * 2 + (size_t)kc * 128 + c * 16;
        cp16(sb + 32768 + doff, (const char*)Bh + boff, v);
    }
}

__global__ __launch_bounds__(256, 2) void gemm_mma(
    const __half* __restrict__ Ah, const __half* __restrict__ Al,
    const __half* __restrict__ Bh,
    float* __restrict__ C, int kcn, int lda, int ldb, int ldc, int Nreal,
    int mode, const float* __restrict__ aux)
{
    extern __shared__ char smem[];
    const uint32_t smem_u = smem_to_u32(smem);
    const int tid  = threadIdx.x;
    const int lane = tid & 31;
    const int wid  = tid >> 5;
    const int wm   = wid & 3;
    const int wn   = wid >> 2;
    const int row0 = blockIdx.y * 128, col0 = blockIdx.x * 128;
    const int kc0  = blockIdx.z * kcn;

    int rowsB = Nreal - col0; if (rowsB > 128) rowsB = 128;

    float acc[2][8][4];
#pragma unroll
    for (int mt = 0; mt < 2; mt++)
#pragma unroll
        for (int nt = 0; nt < 8; nt++)
#pragma unroll
            for (int q = 0; q < 4; q++) acc[mt][nt][q] = 0.f;

    stage_load(smem_u, Ah, Al, Bh, row0, col0, lda, ldb, rowsB, kc0, tid);
    CP_COMMIT();
    if (kcn > 1) {
        stage_load(smem_u + STAGE_BYTES, Ah, Al, Bh, row0, col0, lda, ldb, rowsB, kc0 + 1, tid);
        CP_COMMIT();
    }

    const uint32_t rA_base = wm * 32 + (lane & 15);
    const uint32_t bA_lane = ((lane >> 4) << 4);
    const uint32_t rB_base = wn * 64 + ((lane >> 4) << 3) + (lane & 7);
    const uint32_t bB_lane = (((lane >> 3) & 1) << 4);

    for (int c2 = 0; c2 < kcn; c2++) {
        if (c2 + 1 < kcn) { CP_WAIT1(); } else { CP_WAIT0(); }
        __syncthreads();

        const uint32_t sb = smem_u + (uint32_t)(c2 & 1) * STAGE_BYTES;
#pragma unroll
        for (int ks = 0; ks < 4; ks++) {
            uint32_t ahf[2][4], alf[2][4], bhf[4][4];
#pragma unroll
            for (int mt = 0; mt < 2; mt++) {
                uint32_t aaddr = sb + swz(rA_base + mt * 16, ks * 32 + bA_lane);
                LDSM_X4(ahf[mt][0], ahf[mt][1], ahf[mt][2], ahf[mt][3], aaddr);
                LDSM_X4(alf[mt][0], alf[mt][1], alf[mt][2], alf[mt][3], aaddr + 16384);
            }
#pragma unroll
            for (int p = 0; p < 4; p++) {
                uint32_t baddr = sb + 32768 + swz(rB_base + p * 16, ks * 32 + bB_lane);
                LDSM_X4(bhf[p][0], bhf[p][1], bhf[p][2], bhf[p][3], baddr);
            }
#pragma unroll
            for (int mt = 0; mt < 2; mt++)
#pragma unroll
                for (int nt = 0; nt < 8; nt++) {
                    const uint32_t* b2h = &bhf[nt >> 1][(nt & 1) * 2];
                    mma16816(acc[mt][nt], ahf[mt], b2h);
                    mma16816(acc[mt][nt], alf[mt], b2h);
                }
        }
        __syncthreads();
        if (c2 + 2 < kcn) {
            stage_load(smem_u + (uint32_t)(c2 & 1) * STAGE_BYTES,
                       Ah, Al, Bh, row0, col0, lda, ldb, rowsB, kc0 + c2 + 2, tid);
            CP_COMMIT();
        }
    }

    const int rr = row0 + wm * 32 + (lane >> 2);
    const int cc = col0 + wn * 64 + (lane & 3) * 2;
#pragma unroll
    for (int mt = 0; mt < 2; mt++)
#pragma unroll
        for (int nt = 0; nt < 8; nt++) {
            int colb = cc + nt * 8;
            if (colb < Nreal) {
                float* p0 = &C[(size_t)(rr + mt * 16)     * ldc + colb];
                float* p1 = &C[(size_t)(rr + mt * 16 + 8) * ldc + colb];
                if (mode == 1) {
                    atomicAdd(p0,     acc[mt][nt][0]);
                    atomicAdd(p0 + 1, acc[mt][nt][1]);
                    atomicAdd(p1,     acc[mt][nt][2]);
                    atomicAdd(p1 + 1, acc[mt][nt][3]);
                } else if (mode == 2) {
                    float b0 = aux[colb], b1 = aux[colb + 1];
                    float v[4] = { acc[mt][nt][0] + b0, acc[mt][nt][1] + b1,
                                   acc[mt][nt][2] + b0, acc[mt][nt][3] + b1 };
#pragma unroll
                    for (int q = 0; q < 4; q++) {
                        float sp = (v[q] > 20.f) ? v[q] : __logf(1.f + __expf(v[q]));
                        v[q] = fminf(fmaxf(sp, 1e-4f), 20.f);
                    }
                    *reinterpret_cast<float2*>(p0) = make_float2(v[0], v[1]);
                    *reinterpret_cast<float2*>(p1) = make_float2(v[2], v[3]);
                } else {
                    *reinterpret_cast<float2*>(p0) = make_float2(acc[mt][nt][0], acc[mt][nt][1]);
                    *reinterpret_cast<float2*>(p1) = make_float2(acc[mt][nt][2], acc[mt][nt][3]);
                }
            }
        }
}

// ---------------------------------------------------------------------------
// fp32 -> fp16 hi/lo split helpers
// ---------------------------------------------------------------------------
__device__ __forceinline__ void split1(float x, __half& h, __half& l) {
    h = __float2half_rn(x);
    l = __float2half_rn(x - __half2float(h));
}
__global__ void splitHL_kernel(const float* __restrict__ src,
                               __half* __restrict__ hi,
                               __half* __restrict__ lo, int n)
{
    int i = blockIdx.x * blockDim.x + threadIdx.x;
    if (i < n) split1(src[i], hi[i], lo[i]);
}

// ---------------------------------------------------------------------------
// fused prep: hidden hi/lo split + 4 weight fp16 casts + zero XDBL/out + beta init
// ---------------------------------------------------------------------------
#define P_N0 (NTOK*DM)
#define P_N1 (P_N0 + 2*DI*DM)
#define P_N2 (P_N1 + XDBLC*DI)
#define P_N3 (P_N2 + DI*DTR)
#define P_N4 (P_N3 + DM*DI)
#define P_N5 (P_N4 + NTOK*XDBLC)
#define P_N6 (P_N5 + NTOK*DM)
__global__ void prep_kernel(const float* __restrict__ hidden,
                            const float* __restrict__ W_in,
                            const float* __restrict__ W_x,
                            const float* __restrict__ W_dt,
                            const float* __restrict__ W_out,
                            __half* __restrict__ hidH, __half* __restrict__ hidL,
                            __half* __restrict__ WinH, __half* __restrict__ WxH,
                            __half* __restrict__ WdtH, __half* __restrict__ WoutH,
                            float* __restrict__ XDBL, float* __restrict__ out)
{
    int i = blockIdx.x * blockDim.x + threadIdx.x;
    if (i == 0) g_betaBits = 0xFFFFFFFFu;
    if (i < P_N0)      { split1(hidden[i], hidH[i], hidL[i]); }
    else if (i < P_N1) { int j = i - P_N0; WinH[j]  = __float2half_rn(W_in[j]); }
    else if (i < P_N2) { int j = i - P_N1; WxH[j]   = __float2half_rn(W_x[j]); }
    else if (i < P_N3) { int j = i - P_N2; WdtH[j]  = __float2half_rn(W_dt[j]); }
    else if (i < P_N4) { int j = i - P_N3; WoutH[j] = __float2half_rn(W_out[j]); }
    else if (i < P_N5) { XDBL[i - P_N4] = 0.f; }
    else if (i < P_N6) { out[i - P_N5] = 0.f; }
}

// ---------------------------------------------------------------------------
// causal depthwise conv (k=4) + bias + silu, fused hi/lo split of output
// ---------------------------------------------------------------------------
__global__ void conv_silu_kernel(const float* __restrict__ XZ,
                                 const float* __restrict__ w,
                                 const float* __restrict__ cb,
                                 float* __restrict__ Xc,
                                 __half* __restrict__ XcH,
                                 __half* __restrict__ XcL)
{
    int idx = blockIdx.x * blockDim.x + threadIdx.x;
    if (idx >= NTOK * DI) return;
    int d = idx & (DI - 1);
    int token = idx >> 11;
    int b = token >> 10;
    int l = token & (LL - 1);

    float accv = cb[d];
#pragma unroll
    for (int j = 0; j < 4; j++) {
        int ll = l + j - 3;
        if (ll >= 0)
            accv = fmaf(w[d * 4 + j], XZ[(size_t)(b * LL + ll) * (2 * DI) + d], accv);
    }
    float s = __fdividef(accv, 1.f + __expf(-accv));
    Xc[idx] = s;
    split1(s, XcH[idx], XcL[idx]);
}

// ---------------------------------------------------------------------------
// 3-array tiled transpose [token][d] -> [d][token]  (z: DELTA, Xc, z-half of XZ)
// grid (DI/32, NTOK/32, 3), block (32, 8)
// ---------------------------------------------------------------------------
__global__ void transpose3_kernel(const float* __restrict__ DELTA,
                                  const float* __restrict__ Xc,
                                  const float* __restrict__ XZ,
                                  float* __restrict__ DT_T,
                                  float* __restrict__ XcT,
                                  float* __restrict__ ZT)
{
    __shared__ float tile[32][33];
    int z = blockIdx.z;
    const float* src = (z == 0) ? DELTA : (z == 1) ? Xc : XZ;
    float* dst       = (z == 0) ? DT_T  : (z == 1) ? XcT : ZT;
    int ldsrc        = (z == 2) ? 2 * DI : DI;
    int off          = (z == 2) ? DI : 0;

    int x0 = blockIdx.x * 32;   // d
    int y0 = blockIdx.y * 32;   // token
#pragma unroll
    for (int r = threadIdx.y; r < 32; r += 8)
        tile[r][threadIdx.x] = src[(size_t)(y0 + r) * ldsrc + off + x0 + threadIdx.x];
    __syncthreads();
#pragma unroll
    for (int r = threadIdx.y; r < 32; r += 8)
        dst[(size_t)(x0 + r) * NTOK + y0 + threadIdx.x] = tile[threadIdx.x][r];
}

// ---------------------------------------------------------------------------
// beta: parallel encoded-min over XDBL[:, 64:80]
// ---------------------------------------------------------------------------
__global__ void beta_kernel(const float* __restrict__ XDBL)
{
    unsigned m = 0xFFFFFFFFu;
    int stride = gridDim.x * blockDim.x;
    for (int i = blockIdx.x * blockDim.x + threadIdx.x; i < NTOK * DS; i += stride) {
        int token = i >> 4, n = i & 15;
        unsigned bits = __float_as_uint(XDBL[token * XDBLC + DTR + n]);
        unsigned enc = (bits & 0x80000000u) ? ~bits : (bits | 0x80000000u);
        m = umin(m, enc);
    }
#pragma unroll
    for (int o = 16; o > 0; o >>= 1)
        m = umin(m, __shfl_xor_sync(0xffffffffu, m, o));
    if ((threadIdx.x & 31) == 0) atomicMin(&g_betaBits, m);
}

// ---------------------------------------------------------------------------
// selective scan v3: 16 lanes/seq, 2 seqs/warp, 2048 warps.
// d-streams from transposed arrays (float4 per 4 tokens, prefetched);
// B/C staged through smem per 128-token chunk; batched Y stores.
// grid 256 x 256 threads
// ---------------------------------------------------------------------------
#define TCH 128
__global__ __launch_bounds__(256) void scan_kernel(
    const float* __restrict__ XDBL,
    const float* __restrict__ DT_T, const float* __restrict__ XcT,
    const float* __restrict__ ZT,
    const float* __restrict__ A_log,const float* __restrict__ Dv,
    __half* __restrict__ YH, __half* __restrict__ YL)
{
    __shared__ float sBC[TCH * 32];
    const int tid  = threadIdx.x;
    const int lane = tid & 31;
    const int w    = tid >> 5;
    const int seq  = (blockIdx.x * 8 + w) * 2 + (lane >> 4);
    const int n    = lane & 15;
    const int b    = seq >> 11;
    const int d    = seq & (DI - 1);

    float a  = __expf(A_log[d * DS + n]);
    float Dd = Dv[d];
    float beta;
    {
        unsigned e = g_betaBits;
        unsigned bits = (e & 0x80000000u) ? (e ^ 0x80000000u) : ~e;
        beta = fmaxf(0.f, -__uint_as_float(bits));
    }
    float state = 0.f;

    const size_t rbase = (size_t)d * NTOK + (b << 10);
    const float* dRow = DT_T + rbase;
    const float* xRow = XcT  + rbase;
    const float* zRow = ZT   + rbase;
    const size_t bcBase = (size_t)(b << 10) * XDBLC;

    float4 nd = *(const float4*)&dRow[0];
    float4 nx = *(const float4*)&xRow[0];
    float4 nz = *(const float4*)&zRow[0];

    int l = 0;
    for (int c0 = 0; c0 < LL; c0 += TCH) {
        __syncthreads();
        // stage B/C chunk: 128 tokens x 32 floats (B at +64, C at +80)
#pragma unroll
        for (int i = 0; i < 4; i++) {
            int idx = tid + i * 256;          // 0..1023 float4s
            int tt = idx >> 3, j = idx & 7;
            *(float4*)&sBC[tt * 32 + j * 4] =
                *(const float4*)&XDBL[bcBase + (size_t)(c0 + tt) * XDBLC + DTR + j * 4];
        }
        __syncthreads();

        for (int t4 = 0; t4 < TCH; t4 += 4) {
            const int lg = l;
            float4 d4 = nd, x4 = nx, z4 = nz;
            if (lg + 4 < LL) {
                nd = *(const float4*)&dRow[lg + 4];
                nx = *(const float4*)&xRow[lg + 4];
                nz = *(const float4*)&zRow[lg + 4];
            }
            float dd[4] = {d4.x, d4.y, d4.z, d4.w};
            float xx[4] = {x4.x, x4.y, x4.z, x4.w};
            float zz[4] = {z4.x, z4.y, z4.z, z4.w};
            float yb[4];
#pragma unroll
            for (int u = 0; u < 4; u++) {
                int tt = t4 + u;
                float Bv = sBC[tt * 32 + n] + beta;
                float Cv = sBC[tt * 32 + 16 + n];
                float dA = __expf(-dd[u] * a);
                state = fmaf(dA, state, (dd[u] * xx[u]) * Bv);
                float p = state * Cv;
                p += __shfl_xor_sync(0xffffffffu, p, 1);
                p += __shfl_xor_sync(0xffffffffu, p, 2);
                p += __shfl_xor_sync(0xffffffffu, p, 4);
                p += __shfl_xor_sync(0xffffffffu, p, 8);
                float sz = __fdividef(zz[u], 1.f + __expf(-zz[u]));
                yb[u] = (p + xx[u] * Dd) * sz;
            }
            // batched store: lanes (lane&15)<4 each store one token's hi+lo
            if ((lane & 15) < 4) {
                int u = lane & 3;
                float yv = (u == 0) ? yb[0] : (u == 1) ? yb[1] : (u == 2) ? yb[2] : yb[3];
                __half h, lo;
                split1(yv, h, lo);
                size_t oi = (size_t)((b << 10) + lg + u) * DI + d;
                YH[oi] = h;
                YL[oi] = lo;
            }
            l = lg + 4;
        }
    }
}

// ---------------------------------------------------------------------------
extern "C" void kernel_launch(void* const* d_in, const int* in_sizes, int n_in,
                              void* d_out, int out_size)
{
    const float* hidden  = (const float*)d_in[0];
    const float* W_in    = (const float*)d_in[1];
    const float* conv_w  = (const float*)d_in[2];
    const float* conv_b  = (const float*)d_in[3];
    const float* W_x     = (const float*)d_in[4];
    const float* W_dt    = (const float*)d_in[5];
    const float* dt_bias = (const float*)d_in[6];
    const float* W_out   = (const float*)d_in[7];
    const float* A_log   = (const float*)d_in[8];
    const float* Dv      = (const float*)d_in[9];
    float* out = (float*)d_out;

    float *XZ, *Xc, *XDBL, *DELTA, *DT_T, *XcT, *ZT;
    cudaGetSymbolAddress((void**)&XZ,    g_XZ);
    cudaGetSymbolAddress((void**)&Xc,    g_Xc);
    cudaGetSymbolAddress((void**)&XDBL,  g_XDBL);
    cudaGetSymbolAddress((void**)&DELTA, g_DELTA);
    cudaGetSymbolAddress((void**)&DT_T,  g_DT_T);
    cudaGetSymbolAddress((void**)&XcT,   g_XcT);
    cudaGetSymbolAddress((void**)&ZT,    g_ZT);

    __half *hidH,*hidL,*WinH,*XcH,*XcL,*WxH,*XdH,*XdL,*WdtH,*YH,*YL,*WoutH;
    cudaGetSymbolAddress((void**)&hidH,  g_hidH);  cudaGetSymbolAddress((void**)&hidL,  g_hidL);
    cudaGetSymbolAddress((void**)&WinH,  g_WinH);
    cudaGetSymbolAddress((void**)&XcH,   g_XcH);   cudaGetSymbolAddress((void**)&XcL,   g_XcL);
    cudaGetSymbolAddress((void**)&WxH,   g_WxH);
    cudaGetSymbolAddress((void**)&XdH,   g_XdH);   cudaGetSymbolAddress((void**)&XdL,   g_XdL);
    cudaGetSymbolAddress((void**)&WdtH,  g_WdtH);
    cudaGetSymbolAddress((void**)&YH,    g_YH);    cudaGetSymbolAddress((void**)&YL,    g_YL);
    cudaGetSymbolAddress((void**)&WoutH, g_WoutH);

    cudaFuncSetAttribute(gemm_mma, cudaFuncAttributeMaxDynamicSharedMemorySize, GEMM_SMEM);

    // 0) fused prep: splits + zeros + beta init
    prep_kernel<<<(P_N6 + 255)/256, 256>>>(hidden, W_in, W_x, W_dt, W_out,
                                           hidH, hidL, WinH, WxH, WdtH, WoutH,
                                           XDBL, out);

    // 1) xz = hidden @ W_in^T   (M=2048, N=4096, K=1024)
    gemm_mma<<<dim3(4096/128, NTOK/128, 1), 256, GEMM_SMEM>>>(
        hidH, hidL, WinH, XZ, 16, DM, DM, 2*DI, 2*DI, 0, nullptr);

    // 2) conv + silu (+ split)
    conv_silu_kernel<<<(NTOK*DI)/256, 256>>>(XZ, conv_w, conv_b, Xc, XcH, XcL);

    // 3) x_dbl = Xc @ W_x^T     (M=2048, N=96 pad 128, K=2048, split-K x4)
    gemm_mma<<<dim3(1, NTOK/128, 4), 256, GEMM_SMEM>>>(
        XcH, XcL, WxH, XDBL, 8, DI, DI, XDBLC, XDBLC, 1, nullptr);

    // 4) beta (parallel) — needs only XDBL
    beta_kernel<<<32, 256>>>(XDBL);

    // 5) split x_dbl for GEMM6
    splitHL_kernel<<<(NTOK*XDBLC + 255)/256, 256>>>(XDBL, XdH, XdL, NTOK*XDBLC);

    // 6) dt = x_dbl[:, :64] @ W_dt^T  (K=64; lda=96) with fused softplus+clip
    gemm_mma<<<dim3(DI/128, NTOK/128, 1), 256, GEMM_SMEM>>>(
        XdH, XdL, WdtH, DELTA, 1, XDBLC, DTR, DI, DI, 2, dt_bias);

    // 7) transpose DELTA / Xc / z -> [d][token]
    transpose3_kernel<<<dim3(DI/32, NTOK/32, 3), dim3(32, 8)>>>(
        DELTA, Xc, XZ, DT_T, XcT, ZT);

    // 8) scan v3 (+ gating + split)
    scan_kernel<<<256, 256>>>(XDBL, DT_T, XcT, ZT, A_log, Dv, YH, YL);

    // 9) out = Y @ W_out^T      (M=2048, N=1024, K=2048, split-K x2)
    gemm_mma<<<dim3(DM/128, NTOK/128, 2), 256, GEMM_SMEM>>>(
        YH, YL, WoutH, out, 16, DI, DI, DM, DM, 1, nullptr);
}